// round 12
// baseline (speedup 1.0000x reference)
#include <cuda_runtime.h>

// Problem constants
#define B_    2048
#define T_    512
#define FIN_  32
#define H_    64
#define G4_   256        // 4*H
#define HOR_  48
#define FOUT_ 8
#define NROW  14         // batch rows per CTA
#define NCTA  147        // ceil(2048/14)
#define RT    512
#define G0ROW (B_ * G4_)

typedef unsigned long long u64;

// ---------------- scratch (__device__ globals; no cudaMalloc allowed) ----------------
// d_g0 layout: [t][b][unit*4 + gate]  (float4 per hidden unit = {i,f,g,o})
__device__ float d_g0[(size_t)T_ * B_ * G4_];
__device__ float d_WcT[FIN_ * G4_];    // combined (Wih0 @ W_emb), pidx channel order
__device__ float d_bc[G4_];            // combined layer0 bias, pidx order
__device__ float d_wih0P[H_ * G4_];    // decoder Wih[0], off2-packed
__device__ float d_whh0P[H_ * G4_];    // encoder Whh[0], off2-packed (streamed from L2)
__device__ float d_whh1P[H_ * G4_];    // decoder Whh[1], off2-packed

// ---------------- fast activations ----------------
__device__ __forceinline__ float sigf(float x) {
    return __fdividef(1.0f, 1.0f + __expf(-x));
}
__device__ __forceinline__ float tanh_f(float x) {
    return __fdividef(2.0f, 1.0f + __expf(-2.0f * x)) - 1.0f;
}
__device__ __forceinline__ void lstm4(float gi, float gf, float gg, float go,
                                      float& c, float* __restrict__ hout) {
    float cn = sigf(gf) * c + sigf(gi) * tanh_f(gg);
    c = cn;
    *hout = sigf(go) * tanh_f(cn);
}

// ---------------- packed fp32x2 helpers ----------------
__device__ __forceinline__ u64 fma2(u64 a, u64 b, u64 c) {
    u64 d;
    asm("fma.rn.f32x2 %0, %1, %2, %3;" : "=l"(d) : "l"(a), "l"(b), "l"(c));
    return d;
}
__device__ __forceinline__ float hadd2(u64 a) {
    float lo, hi;
    asm("mov.b64 {%0, %1}, %2;" : "=f"(lo), "=f"(hi) : "l"(a));
    return lo + hi;
}

// packed output-channel index: gate g (0..255) -> unit*4 + gate_slot (x-part layout)
__device__ __forceinline__ int pidx(int g) { return ((g & 63) << 2) + (g >> 6); }
// weight packing W[g][k] -> [(k>>2)][g][k&3]  (one float4 = 4 consecutive k for gate g)
__device__ __forceinline__ int off2(int g, int k) {
    return ((k >> 2) << 10) + (g << 2) + (k & 3);
}

// ---------------- prep: combined weights / packed transposes ----------------
__global__ void prep_kernel(const float* __restrict__ W_emb, const float* __restrict__ b_emb,
                            const float* __restrict__ encWih, const float* __restrict__ encbih,
                            const float* __restrict__ encbhh, const float* __restrict__ encWhh,
                            const float* __restrict__ decWih, const float* __restrict__ decWhh)
{
    int g  = threadIdx.x;   // original gate index 0..255
    int bb = blockIdx.x;    // 0..32
    float wrow[H_];
#pragma unroll
    for (int h = 0; h < H_; h++) wrow[h] = encWih[g * H_ + h];

    if (bb == FIN_) {
        float b = encbih[g] + encbhh[g];
#pragma unroll
        for (int h = 0; h < H_; h++) b = fmaf(wrow[h], b_emb[h], b);
        d_bc[pidx(g)] = b;
#pragma unroll
        for (int k = 0; k < H_; k++) {
            d_wih0P[off2(g, k)] = decWih[g * H_ + k];
            d_whh0P[off2(g, k)] = encWhh[g * H_ + k];
            d_whh1P[off2(g, k)] = decWhh[16384 + g * H_ + k];
        }
    } else {
        int f = bb;
        float s = 0.f;
#pragma unroll
        for (int h = 0; h < H_; h++) s = fmaf(wrow[h], W_emb[h * FIN_ + f], s);
        d_WcT[f * G4_ + pidx(g)] = s;
    }
}

// ---------------- GEMM: d_g0[t][b][c] = X[b][t][:] @ WcT[:, c] + bc[c] ----------------
__global__ void __launch_bounds__(256)
emb_gemm(const float* __restrict__ X)
{
    __shared__ float sX[128 * FIN_];
    const int t   = blockIdx.y;
    const int b0  = blockIdx.x * 128;
    const int tid = threadIdx.x;   // packed channel

#pragma unroll
    for (int q = 0; q < 4; q++) {
        int lin = tid + q * 256;
        int rr = lin >> 3, f4 = lin & 7;
        float4 v = *(const float4*)(X + ((size_t)(b0 + rr) * T_ + t) * FIN_ + f4 * 4);
        *(float4*)(sX + rr * FIN_ + f4 * 4) = v;
    }
    float w[FIN_];
#pragma unroll
    for (int f = 0; f < FIN_; f++) w[f] = d_WcT[f * G4_ + tid];
    const float bias = d_bc[tid];
    __syncthreads();

    float* dst = d_g0 + (size_t)t * B_ * G4_ + (size_t)b0 * G4_ + tid;
#pragma unroll 2
    for (int rr = 0; rr < 128; rr++) {
        float a = bias;
        const float* xr = sX + rr * FIN_;
#pragma unroll
        for (int f = 0; f < FIN_; f += 4) {
            float4 x = *(const float4*)(xr + f);
            a = fmaf(x.x, w[f + 0], a);
            a = fmaf(x.y, w[f + 1], a);
            a = fmaf(x.z, w[f + 2], a);
            a = fmaf(x.w, w[f + 3], a);
        }
        dst[(size_t)rr * G4_] = a;
    }
}

// ---------------- decoder matvec: one smem matrix + one gmem matrix ----------------
// a[r] += sum_k hs[r][k]*Ws[g][k] + hg[r][k]*Wg[g][k], k in [koff*4, koff*4+32)
__device__ __forceinline__ void dec_mv(u64 a[NROW],
                                       const float* __restrict__ sWslot,
                                       const float* __restrict__ sHs,
                                       const float* __restrict__ gW,
                                       const float* __restrict__ sHg,
                                       int g, int koff)
{
    ulonglong2 wg0 = __ldg((const ulonglong2*)(gW + (koff + 0) * 1024 + (g << 2)));
    ulonglong2 wg1 = __ldg((const ulonglong2*)(gW + (koff + 1) * 1024 + (g << 2)));
#pragma unroll
    for (int kc = 0; kc < 8; kc++) {
        ulonglong2 ws = *(const ulonglong2*)(sWslot + (koff + kc) * 1024 + (g << 2));
        ulonglong2 wg = wg0;
        wg0 = wg1;
        if (kc < 6) wg1 = __ldg((const ulonglong2*)(gW + (koff + kc + 2) * 1024 + (g << 2)));
        int ko = (koff + kc) * 4;
#pragma unroll
        for (int r = 0; r < NROW; r++) {
            ulonglong2 hs = *(const ulonglong2*)(sHs + r * 64 + ko);
            ulonglong2 hg = *(const ulonglong2*)(sHg + r * 64 + ko);
            a[r] = fma2(hs.x, ws.x, a[r]);
            a[r] = fma2(hs.y, ws.y, a[r]);
            a[r] = fma2(hg.x, wg.x, a[r]);
            a[r] = fma2(hg.y, wg.y, a[r]);
        }
    }
}

// smem: sW 2*16384 | sH 2*896 | sPa0 sPb0 sPa1 sPb1 each 3584  = 48896 floats
#define SMEM_FLOATS (2*16384 + 2*896 + 4*3584)
#define SMEM_BYTES  (SMEM_FLOATS * 4)

__global__ void __launch_bounds__(RT, 1)
rnn_kernel(const float* __restrict__ encWih, const float* __restrict__ encWhh,
           const float* __restrict__ encbih, const float* __restrict__ encbhh,
           const float* __restrict__ decWih, const float* __restrict__ decWhh,
           const float* __restrict__ decbih, const float* __restrict__ decbhh,
           const float* __restrict__ Wreg,   const float* __restrict__ breg,
           float* __restrict__ out)
{
    extern __shared__ float sm[];
    float* sW   = sm;              // slot0 @0, slot1 @16384 (off2 layout)
    float* sH   = sm + 32768;      // h0 [14][64], h1 @ +896
    float* sPa0 = sm + 34560;      // layer0 partial (kh=0), gate-major [14][256]
    float* sPb0 = sm + 38144;      // layer0 partial (kh=1)
    float* sPa1 = sm + 41728;      // layer1 partial (kh=0)
    float* sPb1 = sm + 45312;      // layer1 partial (kh=1)

    const int tid  = threadIdx.x;
    const int g    = tid & 255;          // gate 0..255
    const int kh   = tid >> 8;           // k-half
    const int koff = kh * 8;             // k-chunk base (k = 4*koff)
    const int b0   = blockIdx.x * NROW;

    // ---- init: pack encoder Wih1 -> slot0, Whh1 -> slot1 ----
    for (int i = tid; i < 16384; i += RT) {
        int gg = i >> 6, k = i & 63;
        int d = off2(gg, k);
        sW[d]         = encWih[16384 + i];
        sW[16384 + d] = encWhh[16384 + i];
    }
    for (int i = tid; i < 2 * 896; i += RT) sH[i] = 0.f;

    // ---- update-cell mapping: cell A = tid (rows 0..7), cell B = tid+512 (rows 8..13) ----
    const int r0 = tid >> 6, u0 = tid & 63;
    const bool hasB = (tid < 384);
    const int r1 = (tid + 512) >> 6, u1 = (tid + 512) & 63;
    int bA = b0 + r0; if (bA >= B_) bA = B_ - 1;
    int bB = b0 + (hasB ? r1 : 0); if (bB >= B_) bB = B_ - 1;
    const size_t gxoA = (size_t)bA * G4_ + (u0 << 2);
    const size_t gxoB = (size_t)bB * G4_ + (u1 << 2);

    // encoder layer-1 biases for the cells
    float4 eb1A, eb1B;
    eb1A.x = encbih[256 + u0]       + encbhh[256 + u0];
    eb1A.y = encbih[320 + u0]       + encbhh[320 + u0];
    eb1A.z = encbih[384 + u0]       + encbhh[384 + u0];
    eb1A.w = encbih[448 + u0]       + encbhh[448 + u0];
    eb1B.x = encbih[256 + u1]       + encbhh[256 + u1];
    eb1B.y = encbih[320 + u1]       + encbhh[320 + u1];
    eb1B.z = encbih[384 + u1]       + encbhh[384 + u1];
    eb1B.w = encbih[448 + u1]       + encbhh[448 + u1];
    __syncthreads();

    float4 gxA = *(const float4*)(d_g0 + gxoA);      // x(0)
    float4 gxB = *(const float4*)(d_g0 + gxoB);
    float c0A = 0.f, c1A = 0.f, c0B = 0.f, c1B = 0.f;

    // ---- prologue: h0(0) from x(0) (h0(-1)=0 so gates0(0)=x(0)) ----
    lstm4(gxA.x, gxA.y, gxA.z, gxA.w, c0A, sH + r0 * 64 + u0);
    if (hasB) lstm4(gxB.x, gxB.y, gxB.z, gxB.w, c0B, sH + r1 * 64 + u1);
    gxA = *(const float4*)(d_g0 + (size_t)1 * G0ROW + gxoA);   // x(1)
    gxB = *(const float4*)(d_g0 + (size_t)1 * G0ROW + gxoB);
    __syncthreads();

    float* q0 = kh ? sPb0 : sPa0;
    float* q1 = kh ? sPb1 : sPa1;

    // -------------------- encoder supersteps s = 0..510 --------------------
    // phase M: gates1(s) partial (Wih1 h0(s) + Whh1 h1(s-1)); gates0raw(s+1) (Whh0 h0(s))
    // phase U: update (c1,h1)(s) and (c0,h0)(s+1)
    for (int s = 0; s < T_ - 1; s++) {
        u64 a0[NROW], a1[NROW];
#pragma unroll
        for (int r = 0; r < NROW; r++) { a0[r] = 0ull; a1[r] = 0ull; }

        ulonglong2 wg0 = __ldg((const ulonglong2*)(d_whh0P + (koff + 0) * 1024 + (g << 2)));
        ulonglong2 wg1 = __ldg((const ulonglong2*)(d_whh0P + (koff + 1) * 1024 + (g << 2)));
#pragma unroll
        for (int kc = 0; kc < 8; kc++) {
            ulonglong2 wi = *(const ulonglong2*)(sW + (koff + kc) * 1024 + (g << 2));
            ulonglong2 wh = *(const ulonglong2*)(sW + 16384 + (koff + kc) * 1024 + (g << 2));
            ulonglong2 w0 = wg0;
            wg0 = wg1;
            if (kc < 6) wg1 = __ldg((const ulonglong2*)(d_whh0P + (koff + kc + 2) * 1024 + (g << 2)));
            int ko = (koff + kc) * 4;
#pragma unroll
            for (int r = 0; r < NROW; r++) {
                ulonglong2 h0v = *(const ulonglong2*)(sH + r * 64 + ko);
                ulonglong2 h1v = *(const ulonglong2*)(sH + 896 + r * 64 + ko);
                a1[r] = fma2(h0v.x, wi.x, a1[r]);
                a1[r] = fma2(h0v.y, wi.y, a1[r]);
                a1[r] = fma2(h1v.x, wh.x, a1[r]);
                a1[r] = fma2(h1v.y, wh.y, a1[r]);
                a0[r] = fma2(h0v.x, w0.x, a0[r]);
                a0[r] = fma2(h0v.y, w0.y, a0[r]);
            }
        }
#pragma unroll
        for (int r = 0; r < NROW; r++) {
            q1[r * G4_ + g] = hadd2(a1[r]);
            q0[r * G4_ + g] = hadd2(a0[r]);
        }
        __syncthreads();

        // ---- phase U ----
        {
            int base = r0 * G4_ + u0;
            float gi = sPa1[base]       + sPb1[base]       + eb1A.x;
            float gf = sPa1[base + 64]  + sPb1[base + 64]  + eb1A.y;
            float gg = sPa1[base + 128] + sPb1[base + 128] + eb1A.z;
            float go = sPa1[base + 192] + sPb1[base + 192] + eb1A.w;
            lstm4(gi, gf, gg, go, c1A, sH + 896 + r0 * 64 + u0);
            gi = sPa0[base]       + sPb0[base]       + gxA.x;
            gf = sPa0[base + 64]  + sPb0[base + 64]  + gxA.y;
            gg = sPa0[base + 128] + sPb0[base + 128] + gxA.z;
            go = sPa0[base + 192] + sPb0[base + 192] + gxA.w;
            lstm4(gi, gf, gg, go, c0A, sH + r0 * 64 + u0);
        }
        if (hasB) {
            int base = r1 * G4_ + u1;
            float gi = sPa1[base]       + sPb1[base]       + eb1B.x;
            float gf = sPa1[base + 64]  + sPb1[base + 64]  + eb1B.y;
            float gg = sPa1[base + 128] + sPb1[base + 128] + eb1B.z;
            float go = sPa1[base + 192] + sPb1[base + 192] + eb1B.w;
            lstm4(gi, gf, gg, go, c1B, sH + 896 + r1 * 64 + u1);
            gi = sPa0[base]       + sPb0[base]       + gxB.x;
            gf = sPa0[base + 64]  + sPb0[base + 64]  + gxB.y;
            gg = sPa0[base + 128] + sPb0[base + 128] + gxB.z;
            go = sPa0[base + 192] + sPb0[base + 192] + gxB.w;
            lstm4(gi, gf, gg, go, c0B, sH + r1 * 64 + u1);
        }
        if (s + 2 < T_) {   // prefetch x(s+2) for next U
            gxA = *(const float4*)(d_g0 + (size_t)(s + 2) * G0ROW + gxoA);
            gxB = *(const float4*)(d_g0 + (size_t)(s + 2) * G0ROW + gxoB);
        }
        __syncthreads();
    }

    // ---- epilogue: gates1(511) only -> h1(511) ----
    {
        u64 a1[NROW];
#pragma unroll
        for (int r = 0; r < NROW; r++) a1[r] = 0ull;
#pragma unroll
        for (int kc = 0; kc < 8; kc++) {
            ulonglong2 wi = *(const ulonglong2*)(sW + (koff + kc) * 1024 + (g << 2));
            ulonglong2 wh = *(const ulonglong2*)(sW + 16384 + (koff + kc) * 1024 + (g << 2));
            int ko = (koff + kc) * 4;
#pragma unroll
            for (int r = 0; r < NROW; r++) {
                ulonglong2 h0v = *(const ulonglong2*)(sH + r * 64 + ko);
                ulonglong2 h1v = *(const ulonglong2*)(sH + 896 + r * 64 + ko);
                a1[r] = fma2(h0v.x, wi.x, a1[r]);
                a1[r] = fma2(h0v.y, wi.y, a1[r]);
                a1[r] = fma2(h1v.x, wh.x, a1[r]);
                a1[r] = fma2(h1v.y, wh.y, a1[r]);
            }
        }
#pragma unroll
        for (int r = 0; r < NROW; r++) q1[r * G4_ + g] = hadd2(a1[r]);
        __syncthreads();
        {
            int base = r0 * G4_ + u0;
            float gi = sPa1[base]       + sPb1[base]       + eb1A.x;
            float gf = sPa1[base + 64]  + sPb1[base + 64]  + eb1A.y;
            float gg = sPa1[base + 128] + sPb1[base + 128] + eb1A.z;
            float go = sPa1[base + 192] + sPb1[base + 192] + eb1A.w;
            lstm4(gi, gf, gg, go, c1A, sH + 896 + r0 * 64 + u0);
        }
        if (hasB) {
            int base = r1 * G4_ + u1;
            float gi = sPa1[base]       + sPb1[base]       + eb1B.x;
            float gf = sPa1[base + 64]  + sPb1[base + 64]  + eb1B.y;
            float gg = sPa1[base + 128] + sPb1[base + 128] + eb1B.z;
            float go = sPa1[base + 192] + sPb1[base + 192] + eb1B.w;
            lstm4(gi, gf, gg, go, c1B, sH + 896 + r1 * 64 + u1);
        }
        __syncthreads();
    }

    // -------------------- decoder setup --------------------
    // smem: slot0 := dWhh0, slot1 := dWih1 ; gmem: d_wih0P (dWih0), d_whh1P (dWhh1)
    for (int i = tid; i < 16384; i += RT) {
        int gg = i >> 6, k = i & 63;
        int d = off2(gg, k);
        sW[d]         = decWhh[i];
        sW[16384 + d] = decWih[16384 + i];
    }
    float4 db0A, db0B, db1A, db1B;
    db0A.x = decbih[u0]        + decbhh[u0];
    db0A.y = decbih[64 + u0]   + decbhh[64 + u0];
    db0A.z = decbih[128 + u0]  + decbhh[128 + u0];
    db0A.w = decbih[192 + u0]  + decbhh[192 + u0];
    db0B.x = decbih[u1]        + decbhh[u1];
    db0B.y = decbih[64 + u1]   + decbhh[64 + u1];
    db0B.z = decbih[128 + u1]  + decbhh[128 + u1];
    db0B.w = decbih[192 + u1]  + decbhh[192 + u1];
    db1A.x = decbih[256 + u0]  + decbhh[256 + u0];
    db1A.y = decbih[320 + u0]  + decbhh[320 + u0];
    db1A.z = decbih[384 + u0]  + decbhh[384 + u0];
    db1A.w = decbih[448 + u0]  + decbhh[448 + u0];
    db1B.x = decbih[256 + u1]  + decbhh[256 + u1];
    db1B.y = decbih[320 + u1]  + decbhh[320 + u1];
    db1B.z = decbih[384 + u1]  + decbhh[384 + u1];
    db1B.w = decbih[448 + u1]  + decbhh[448 + u1];
    c0A = c1A = c0B = c1B = 0.f;     // c reset; h carries over from encoder
    __syncthreads();

    // -------------------- decoder: 48 steps --------------------
    for (int t = 0; t < HOR_; t++) {
        // ---- M0: gates0 = dWhh0(smem)·h0 + dWih0(gmem)·h1 ----
        {
            u64 a[NROW];
#pragma unroll
            for (int r = 0; r < NROW; r++) a[r] = 0ull;
            dec_mv(a, sW, sH, d_wih0P, sH + 896, g, koff);
#pragma unroll
            for (int r = 0; r < NROW; r++) q0[r * G4_ + g] = hadd2(a[r]);
        }
        __syncthreads();
        // ---- U0 ----
        {
            int base = r0 * G4_ + u0;
            float gi = sPa0[base]       + sPb0[base]       + db0A.x;
            float gf = sPa0[base + 64]  + sPb0[base + 64]  + db0A.y;
            float gg = sPa0[base + 128] + sPb0[base + 128] + db0A.z;
            float go = sPa0[base + 192] + sPb0[base + 192] + db0A.w;
            lstm4(gi, gf, gg, go, c0A, sH + r0 * 64 + u0);
        }
        if (hasB) {
            int base = r1 * G4_ + u1;
            float gi = sPa0[base]       + sPb0[base]       + db0B.x;
            float gf = sPa0[base + 64]  + sPb0[base + 64]  + db0B.y;
            float gg = sPa0[base + 128] + sPb0[base + 128] + db0B.z;
            float go = sPa0[base + 192] + sPb0[base + 192] + db0B.w;
            lstm4(gi, gf, gg, go, c0B, sH + r1 * 64 + u1);
        }
        __syncthreads();
        // ---- M1: gates1 = dWih1(smem)·h0 + dWhh1(gmem)·h1 ----
        {
            u64 a[NROW];
#pragma unroll
            for (int r = 0; r < NROW; r++) a[r] = 0ull;
            dec_mv(a, sW + 16384, sH, d_whh1P, sH + 896, g, koff);
#pragma unroll
            for (int r = 0; r < NROW; r++) q1[r * G4_ + g] = hadd2(a[r]);
        }
        __syncthreads();
        // ---- U1 ----
        {
            int base = r0 * G4_ + u0;
            float gi = sPa1[base]       + sPb1[base]       + db1A.x;
            float gf = sPa1[base + 64]  + sPb1[base + 64]  + db1A.y;
            float gg = sPa1[base + 128] + sPb1[base + 128] + db1A.z;
            float go = sPa1[base + 192] + sPb1[base + 192] + db1A.w;
            lstm4(gi, gf, gg, go, c1A, sH + 896 + r0 * 64 + u0);
        }
        if (hasB) {
            int base = r1 * G4_ + u1;
            float gi = sPa1[base]       + sPb1[base]       + db1B.x;
            float gf = sPa1[base + 64]  + sPb1[base + 64]  + db1B.y;
            float gg = sPa1[base + 128] + sPb1[base + 128] + db1B.z;
            float go = sPa1[base + 192] + sPb1[base + 192] + db1B.w;
            lstm4(gi, gf, gg, go, c1B, sH + 896 + r1 * 64 + u1);
        }
        __syncthreads();
        // ---- regression head: y = h1 @ Wreg^T + breg (reads only; no sync needed) ----
        if (tid < NROW * FOUT_) {
            int r = tid >> 3, o = tid & 7;
            int b = b0 + r;
            if (b < B_) {
                float a = __ldg(&breg[o]);
                const float* hr = sH + 896 + r * 64;
#pragma unroll
                for (int k = 0; k < H_; k += 4) {
                    float4 h4 = *(const float4*)(hr + k);
                    float4 w4 = __ldg((const float4*)(Wreg + o * H_ + k));
                    a = fmaf(h4.x, w4.x, a);
                    a = fmaf(h4.y, w4.y, a);
                    a = fmaf(h4.z, w4.z, a);
                    a = fmaf(h4.w, w4.w, a);
                }
                out[((size_t)b * HOR_ + t) * FOUT_ + o] = a;
            }
        }
    }
}

// ---------------- launch ----------------
extern "C" void kernel_launch(void* const* d_in, const int* in_sizes, int n_in,
                              void* d_out, int out_size)
{
    const float* X      = (const float*)d_in[0];
    // d_in[1] = X_mask : all-ones, unused by reference
    const float* W_emb  = (const float*)d_in[2];
    const float* b_emb  = (const float*)d_in[3];
    const float* encWih = (const float*)d_in[4];
    const float* encWhh = (const float*)d_in[5];
    const float* encbih = (const float*)d_in[6];
    const float* encbhh = (const float*)d_in[7];
    const float* decWih = (const float*)d_in[8];
    const float* decWhh = (const float*)d_in[9];
    const float* decbih = (const float*)d_in[10];
    const float* decbhh = (const float*)d_in[11];
    const float* W_reg  = (const float*)d_in[12];
    const float* b_reg  = (const float*)d_in[13];
    float* out = (float*)d_out;

    cudaFuncSetAttribute(rnn_kernel, cudaFuncAttributeMaxDynamicSharedMemorySize, SMEM_BYTES);

    prep_kernel<<<FIN_ + 1, 256>>>(W_emb, b_emb, encWih, encbih, encbhh, encWhh,
                                   decWih, decWhh);
    emb_gemm<<<dim3(B_ / 128, T_), 256>>>(X);
    rnn_kernel<<<NCTA, RT, SMEM_BYTES>>>(encWih, encWhh, encbih, encbhh,
                                         decWih, decWhh, decbih, decbhh,
                                         W_reg, b_reg, out);
}